// round 1
// baseline (speedup 1.0000x reference)
#include <cuda_runtime.h>
#include <cuda_bf16.h>

// PositionalSparseLinear: out[b,o] = sum_k x[b, conn[o,k]] * w[o,k]
//   x:     [1024, 8192] f32
//   conn:  [8192, 32]   i32
//   w:     [8192, 32]   f32
//   out:   [1024, 8192] f32
//
// Strategy: batch-tile BT=6 rows of x staged in 192KB SMEM (row-major,
// coalesced fill). One thread per output column; 32 SMEM gathers x 6 FMAs.
// All random-gather traffic hits the SMEM crossbar instead of L2 sectors.

#define IN_F   8192
#define OUT_F  8192
#define KW     32
#define BATCH  1024
#define BT     6
#define THREADS 256
#define O_PER_CTA 2048
#define SMEM_BYTES (IN_F * BT * (int)sizeof(float))   // 196608 bytes

__global__ __launch_bounds__(THREADS, 1)
void psl_kernel(const float* __restrict__ x,
                const int*   __restrict__ conn,
                const float* __restrict__ w,
                float*       __restrict__ out)
{
    extern __shared__ float xs[];   // [BT][IN_F] row-major

    const int tid  = threadIdx.x;
    const int b0   = blockIdx.y * BT;
    int rows = BATCH - b0;
    if (rows > BT) rows = BT;

    // ---- Stage x[b0 .. b0+rows) into SMEM, zero-fill tail rows ----
    // float4 gmem loads (coalesced), float4 smem stores (conflict-free).
    const int V = IN_F / 4;
    for (int idx = tid; idx < BT * V; idx += THREADS) {
        const int r  = idx / V;
        const int c4 = idx - r * V;
        float4 v;
        if (r < rows) {
            v = reinterpret_cast<const float4*>(x + (size_t)(b0 + r) * IN_F)[c4];
        } else {
            v = make_float4(0.f, 0.f, 0.f, 0.f);
        }
        reinterpret_cast<float4*>(xs + (size_t)r * IN_F)[c4] = v;
    }
    __syncthreads();

    const int o_base = blockIdx.x * O_PER_CTA;

    #pragma unroll 1
    for (int oi = 0; oi < O_PER_CTA; oi += THREADS) {
        const int o = o_base + oi + tid;

        const int4*   cp = reinterpret_cast<const int4*>(conn + (size_t)o * KW);
        const float4* wp = reinterpret_cast<const float4*>(w    + (size_t)o * KW);

        float acc0 = 0.f, acc1 = 0.f, acc2 = 0.f,
              acc3 = 0.f, acc4 = 0.f, acc5 = 0.f;

        #pragma unroll
        for (int kk = 0; kk < KW / 4; kk++) {
            const int4   c  = cp[kk];
            const float4 wv = wp[kk];

            #define PSL_STEP(C, WV) {                       \
                const float* p = xs + (C);                  \
                acc0 += (WV) * p[0 * IN_F];                 \
                acc1 += (WV) * p[1 * IN_F];                 \
                acc2 += (WV) * p[2 * IN_F];                 \
                acc3 += (WV) * p[3 * IN_F];                 \
                acc4 += (WV) * p[4 * IN_F];                 \
                acc5 += (WV) * p[5 * IN_F];                 \
            }
            PSL_STEP(c.x, wv.x);
            PSL_STEP(c.y, wv.y);
            PSL_STEP(c.z, wv.z);
            PSL_STEP(c.w, wv.w);
            #undef PSL_STEP
        }

        float* op = out + (size_t)b0 * OUT_F + o;
        if (rows == BT) {
            op[0 * (size_t)OUT_F] = acc0;
            op[1 * (size_t)OUT_F] = acc1;
            op[2 * (size_t)OUT_F] = acc2;
            op[3 * (size_t)OUT_F] = acc3;
            op[4 * (size_t)OUT_F] = acc4;
            op[5 * (size_t)OUT_F] = acc5;
        } else {
            if (rows > 0) op[0 * (size_t)OUT_F] = acc0;
            if (rows > 1) op[1 * (size_t)OUT_F] = acc1;
            if (rows > 2) op[2 * (size_t)OUT_F] = acc2;
            if (rows > 3) op[3 * (size_t)OUT_F] = acc3;
            if (rows > 4) op[4 * (size_t)OUT_F] = acc4;
            if (rows > 5) op[5 * (size_t)OUT_F] = acc5;
        }
    }
}

extern "C" void kernel_launch(void* const* d_in, const int* in_sizes, int n_in,
                              void* d_out, int out_size)
{
    const float* x    = (const float*)d_in[0];   // [1024, 8192] f32
    const int*   conn = (const int*)  d_in[1];   // [8192, 32]   i32
    const float* w    = (const float*)d_in[2];   // [8192, 32]   f32
    float*       out  = (float*)d_out;           // [1024, 8192] f32

    (void)in_sizes; (void)n_in; (void)out_size;

    cudaFuncSetAttribute(psl_kernel,
                         cudaFuncAttributeMaxDynamicSharedMemorySize,
                         SMEM_BYTES);

    dim3 grid(OUT_F / O_PER_CTA, (BATCH + BT - 1) / BT);   // (4, 171)
    psl_kernel<<<grid, THREADS, SMEM_BYTES>>>(x, conn, w, out);
}

// round 2
// speedup vs baseline: 1.0509x; 1.0509x over previous
#include <cuda_runtime.h>
#include <cuda_bf16.h>

// PositionalSparseLinear: out[b,o] = sum_k x[b, conn[o,k]] * w[o,k]
//   x:     [1024, 8192] f32
//   conn:  [8192, 32]   i32
//   w:     [8192, 32]   f32
//   out:   [1024, 8192] f32
//
// Round 2: transposed SMEM batch-tile. xs4[col] holds 4 batch rows of that
// column (float4). One LDS.128 gathers 4 rows at once: ~1.85 crossbar
// phases/row vs 3.4 for the row-major LDS.32 scheme. 512 threads for issue
// coverage. BATCH % 4 == 0 -> no tail path.

#define IN_F   8192
#define OUT_F  8192
#define KW     32
#define BATCH  1024
#define BT     4
#define THREADS 512
#define O_PER_CTA 2048
#define SMEM_BYTES (IN_F * BT * (int)sizeof(float))   // 131072 bytes

__global__ __launch_bounds__(THREADS, 1)
void psl_kernel(const float* __restrict__ x,
                const int*   __restrict__ conn,
                const float* __restrict__ w,
                float*       __restrict__ out)
{
    extern __shared__ float4 xs4[];   // xs4[col] = {x[b0+0..b0+3][col]}

    const int tid = threadIdx.x;
    const int b0  = blockIdx.y * BT;

    // ---- Stage: 4 coalesced row-loads per column, one STS.128 ----
    const float* xr0 = x + (size_t)(b0 + 0) * IN_F;
    const float* xr1 = x + (size_t)(b0 + 1) * IN_F;
    const float* xr2 = x + (size_t)(b0 + 2) * IN_F;
    const float* xr3 = x + (size_t)(b0 + 3) * IN_F;

    #pragma unroll
    for (int c = tid; c < IN_F; c += THREADS) {
        float4 v;
        v.x = xr0[c];
        v.y = xr1[c];
        v.z = xr2[c];
        v.w = xr3[c];
        xs4[c] = v;   // consecutive lanes -> consecutive 16B: conflict-free
    }
    __syncthreads();

    const int o_base = blockIdx.x * O_PER_CTA;

    #pragma unroll 1
    for (int oi = 0; oi < O_PER_CTA; oi += THREADS) {
        const int o = o_base + oi + tid;

        const int4*   cp = reinterpret_cast<const int4*>(conn + (size_t)o * KW);
        const float4* wp = reinterpret_cast<const float4*>(w    + (size_t)o * KW);

        float a0 = 0.f, a1 = 0.f, a2 = 0.f, a3 = 0.f;

        #pragma unroll
        for (int kk = 0; kk < KW / 4; kk++) {
            const int4   c  = cp[kk];
            const float4 wv = wp[kk];

            #define PSL_STEP(C, WV) {                    \
                const float4 xv = xs4[(C)];              \
                a0 = fmaf((WV), xv.x, a0);               \
                a1 = fmaf((WV), xv.y, a1);               \
                a2 = fmaf((WV), xv.z, a2);               \
                a3 = fmaf((WV), xv.w, a3);               \
            }
            PSL_STEP(c.x, wv.x);
            PSL_STEP(c.y, wv.y);
            PSL_STEP(c.z, wv.z);
            PSL_STEP(c.w, wv.w);
            #undef PSL_STEP
        }

        float* op = out + (size_t)b0 * OUT_F + o;
        op[0 * (size_t)OUT_F] = a0;
        op[1 * (size_t)OUT_F] = a1;
        op[2 * (size_t)OUT_F] = a2;
        op[3 * (size_t)OUT_F] = a3;
    }
}

extern "C" void kernel_launch(void* const* d_in, const int* in_sizes, int n_in,
                              void* d_out, int out_size)
{
    const float* x    = (const float*)d_in[0];   // [1024, 8192] f32
    const int*   conn = (const int*)  d_in[1];   // [8192, 32]   i32
    const float* w    = (const float*)d_in[2];   // [8192, 32]   f32
    float*       out  = (float*)d_out;           // [1024, 8192] f32

    (void)in_sizes; (void)n_in; (void)out_size;

    cudaFuncSetAttribute(psl_kernel,
                         cudaFuncAttributeMaxDynamicSharedMemorySize,
                         SMEM_BYTES);

    dim3 grid(OUT_F / O_PER_CTA, BATCH / BT);   // (4, 256)
    psl_kernel<<<grid, THREADS, SMEM_BYTES>>>(x, conn, w, out);
}

// round 4
// speedup vs baseline: 1.7251x; 1.6415x over previous
#include <cuda_runtime.h>
#include <cuda_fp16.h>
#include <cstring>

// PositionalSparseLinear: out[b,o] = sum_k x[b, conn[o,k]] * w[o,k]
//   x:     [1024, 8192] f32
//   conn:  [8192, 32]   i32
//   w:     [8192, 32]   f32
//   out:   [1024, 8192] f32
//
// Round 4 (= round 3 theory, compile fix): fp16-staged transposed SMEM
// batch-tile. xs[col] holds 8 batch rows of that column as 8 halves (16B).
// One random LDS.128 delivers 8 rows -> 2x less crossbar traffic than the
// fp32/BT=4 version. Weights + accumulation stay fp32.

#define IN_F   8192
#define OUT_F  8192
#define KW     32
#define BATCH  1024
#define BT     8
#define THREADS 512
#define O_PER_CTA 2048
#define SMEM_BYTES (IN_F * BT * (int)sizeof(__half))   // 131072 bytes

static __device__ __forceinline__ __half2 u32_as_h2(unsigned int u) {
    __half2 h;
    memcpy(&h, &u, sizeof(h));
    return h;
}

__global__ __launch_bounds__(THREADS, 1)
void psl_kernel(const float* __restrict__ x,
                const int*   __restrict__ conn,
                const float* __restrict__ w,
                float*       __restrict__ out)
{
    extern __shared__ uint4 xs[];   // xs[col] = 8 halves: rows b0..b0+7 of col

    const int tid = threadIdx.x;
    const int b0  = blockIdx.y * BT;

    // ---- Stage: 8 coalesced row-loads per column -> fp16 pack -> STS.128 ----
    const float* xb = x + (size_t)b0 * IN_F;

    #pragma unroll
    for (int c = tid; c < IN_F; c += THREADS) {
        float r0 = xb[c + 0 * (size_t)IN_F];
        float r1 = xb[c + 1 * (size_t)IN_F];
        float r2 = xb[c + 2 * (size_t)IN_F];
        float r3 = xb[c + 3 * (size_t)IN_F];
        float r4 = xb[c + 4 * (size_t)IN_F];
        float r5 = xb[c + 5 * (size_t)IN_F];
        float r6 = xb[c + 6 * (size_t)IN_F];
        float r7 = xb[c + 7 * (size_t)IN_F];

        __half2 h0 = __floats2half2_rn(r0, r1);
        __half2 h1 = __floats2half2_rn(r2, r3);
        __half2 h2 = __floats2half2_rn(r4, r5);
        __half2 h3 = __floats2half2_rn(r6, r7);

        uint4 v;
        memcpy(&v.x, &h0, 4);
        memcpy(&v.y, &h1, 4);
        memcpy(&v.z, &h2, 4);
        memcpy(&v.w, &h3, 4);
        xs[c] = v;   // consecutive lanes -> consecutive 16B: conflict-free
    }
    __syncthreads();

    const int o_base = blockIdx.x * O_PER_CTA;

    #pragma unroll 1
    for (int oi = 0; oi < O_PER_CTA; oi += THREADS) {
        const int o = o_base + oi + tid;

        const int4*   cp = reinterpret_cast<const int4*>(conn + (size_t)o * KW);
        const float4* wp = reinterpret_cast<const float4*>(w    + (size_t)o * KW);

        float a0 = 0.f, a1 = 0.f, a2 = 0.f, a3 = 0.f;
        float a4 = 0.f, a5 = 0.f, a6 = 0.f, a7 = 0.f;

        #pragma unroll
        for (int kk = 0; kk < KW / 4; kk++) {
            const int4   c  = cp[kk];
            const float4 wv = wp[kk];

            #define PSL_STEP(C, WV) {                             \
                const uint4 hv = xs[(C)];                         \
                float2 f0 = __half22float2(u32_as_h2(hv.x));      \
                float2 f1 = __half22float2(u32_as_h2(hv.y));      \
                float2 f2 = __half22float2(u32_as_h2(hv.z));      \
                float2 f3 = __half22float2(u32_as_h2(hv.w));      \
                a0 = fmaf((WV), f0.x, a0);                        \
                a1 = fmaf((WV), f0.y, a1);                        \
                a2 = fmaf((WV), f1.x, a2);                        \
                a3 = fmaf((WV), f1.y, a3);                        \
                a4 = fmaf((WV), f2.x, a4);                        \
                a5 = fmaf((WV), f2.y, a5);                        \
                a6 = fmaf((WV), f3.x, a6);                        \
                a7 = fmaf((WV), f3.y, a7);                        \
            }
            PSL_STEP(c.x, wv.x);
            PSL_STEP(c.y, wv.y);
            PSL_STEP(c.z, wv.z);
            PSL_STEP(c.w, wv.w);
            #undef PSL_STEP
        }

        float* op = out + (size_t)b0 * OUT_F + o;
        op[0 * (size_t)OUT_F] = a0;
        op[1 * (size_t)OUT_F] = a1;
        op[2 * (size_t)OUT_F] = a2;
        op[3 * (size_t)OUT_F] = a3;
        op[4 * (size_t)OUT_F] = a4;
        op[5 * (size_t)OUT_F] = a5;
        op[6 * (size_t)OUT_F] = a6;
        op[7 * (size_t)OUT_F] = a7;
    }
}

extern "C" void kernel_launch(void* const* d_in, const int* in_sizes, int n_in,
                              void* d_out, int out_size)
{
    const float* x    = (const float*)d_in[0];   // [1024, 8192] f32
    const int*   conn = (const int*)  d_in[1];   // [8192, 32]   i32
    const float* w    = (const float*)d_in[2];   // [8192, 32]   f32
    float*       out  = (float*)d_out;           // [1024, 8192] f32

    (void)in_sizes; (void)n_in; (void)out_size;

    cudaFuncSetAttribute(psl_kernel,
                         cudaFuncAttributeMaxDynamicSharedMemorySize,
                         SMEM_BYTES);

    dim3 grid(OUT_F / O_PER_CTA, BATCH / BT);   // (4, 128)
    psl_kernel<<<grid, THREADS, SMEM_BYTES>>>(x, conn, w, out);
}

// round 5
// speedup vs baseline: 3.2302x; 1.8725x over previous
#include <cuda_runtime.h>
#include <cuda_fp16.h>
#include <cstring>

// PositionalSparseLinear: out[b,o] = sum_k x[b, conn[o,k]] * w[o,k]
//   x: [1024,8192] f32   conn: [8192,32] i32   w: [8192,32] f32   out: [1024,8192] f32
//
// Round 5:
//  - fp16-staged transposed SMEM batch tile (BT=8 rows per 16B column) as in R4.
//  - NEW: conn+w packed into cwT[k][o] = (idx<<16)|half(w) by a prep kernel.
//    Main-loop metadata read = one coalesced LDG.32/warp/k (1 wavefront)
//    instead of divergent int4/float4 (32 wavefronts) -> removes ~8.4M of
//    ~17.8M L1tex wavefronts.
//  - 1024 threads/CTA (32 warps/SM), grid (8,128): 6.9 waves, ~1% tail loss.

#define IN_F   8192
#define OUT_F  8192
#define KW     32
#define BATCH  1024
#define BT     8
#define THREADS 1024
#define O_SPLIT 8
#define O_PER_CTA (OUT_F / O_SPLIT)     // 1024 == THREADS
#define SMEM_BYTES (IN_F * BT * (int)sizeof(__half))   // 131072

__device__ unsigned int g_cwT[KW * OUT_F];   // [k][o] packed (idx<<16)|half(w)

static __device__ __forceinline__ __half2 u32_as_h2(unsigned int u) {
    __half2 h; memcpy(&h, &u, sizeof(h)); return h;
}

__global__ void psl_prep(const int* __restrict__ conn, const float* __restrict__ w)
{
    const int idx = blockIdx.x * blockDim.x + threadIdx.x;   // 0 .. 262143
    const int k = idx >> 13;          // / 8192
    const int o = idx & (OUT_F - 1);  // coalesced writes over o
    const int   c  = conn[(size_t)o * KW + k];
    const float wv = w   [(size_t)o * KW + k];
    const unsigned short hb = __half_as_ushort(__float2half_rn(wv));
    g_cwT[(size_t)k * OUT_F + o] = ((unsigned int)c << 16) | (unsigned int)hb;
}

__global__ __launch_bounds__(THREADS, 1)
void psl_main(const float* __restrict__ x, float* __restrict__ out)
{
    extern __shared__ uint4 xs[];   // xs[col] = 8 halves: rows b0..b0+7 of col

    const int tid = threadIdx.x;
    const int b0  = blockIdx.y * BT;

    // ---- Stage: 8 coalesced row-loads per column -> fp16 pack -> STS.128 ----
    const float* xb = x + (size_t)b0 * IN_F;

    #pragma unroll
    for (int c = tid; c < IN_F; c += THREADS) {
        float r0 = xb[c + 0 * (size_t)IN_F];
        float r1 = xb[c + 1 * (size_t)IN_F];
        float r2 = xb[c + 2 * (size_t)IN_F];
        float r3 = xb[c + 3 * (size_t)IN_F];
        float r4 = xb[c + 4 * (size_t)IN_F];
        float r5 = xb[c + 5 * (size_t)IN_F];
        float r6 = xb[c + 6 * (size_t)IN_F];
        float r7 = xb[c + 7 * (size_t)IN_F];

        __half2 h0 = __floats2half2_rn(r0, r1);
        __half2 h1 = __floats2half2_rn(r2, r3);
        __half2 h2 = __floats2half2_rn(r4, r5);
        __half2 h3 = __floats2half2_rn(r6, r7);

        uint4 v;
        memcpy(&v.x, &h0, 4);
        memcpy(&v.y, &h1, 4);
        memcpy(&v.z, &h2, 4);
        memcpy(&v.w, &h3, 4);
        xs[c] = v;
    }
    __syncthreads();

    const int o = blockIdx.x * O_PER_CTA + tid;   // one output per thread
    const unsigned int* __restrict__ cwp = g_cwT + o;

    float a0 = 0.f, a1 = 0.f, a2 = 0.f, a3 = 0.f;
    float a4 = 0.f, a5 = 0.f, a6 = 0.f, a7 = 0.f;

    #pragma unroll 8
    for (int k = 0; k < KW; k++) {
        const unsigned int cw = cwp[(size_t)k * OUT_F];  // coalesced, L2-hot
        const int   c  = (int)(cw >> 16);
        const float wv = __half2float(__ushort_as_half((unsigned short)(cw & 0xffffu)));

        const uint4 hv = xs[c];
        float2 f0 = __half22float2(u32_as_h2(hv.x));
        float2 f1 = __half22float2(u32_as_h2(hv.y));
        float2 f2 = __half22float2(u32_as_h2(hv.z));
        float2 f3 = __half22float2(u32_as_h2(hv.w));
        a0 = fmaf(wv, f0.x, a0);
        a1 = fmaf(wv, f0.y, a1);
        a2 = fmaf(wv, f1.x, a2);
        a3 = fmaf(wv, f1.y, a3);
        a4 = fmaf(wv, f2.x, a4);
        a5 = fmaf(wv, f2.y, a5);
        a6 = fmaf(wv, f3.x, a6);
        a7 = fmaf(wv, f3.y, a7);
    }

    float* op = out + (size_t)b0 * OUT_F + o;
    op[0 * (size_t)OUT_F] = a0;
    op[1 * (size_t)OUT_F] = a1;
    op[2 * (size_t)OUT_F] = a2;
    op[3 * (size_t)OUT_F] = a3;
    op[4 * (size_t)OUT_F] = a4;
    op[5 * (size_t)OUT_F] = a5;
    op[6 * (size_t)OUT_F] = a6;
    op[7 * (size_t)OUT_F] = a7;
}

extern "C" void kernel_launch(void* const* d_in, const int* in_sizes, int n_in,
                              void* d_out, int out_size)
{
    const float* x    = (const float*)d_in[0];   // [1024, 8192] f32
    const int*   conn = (const int*)  d_in[1];   // [8192, 32]   i32
    const float* w    = (const float*)d_in[2];   // [8192, 32]   f32
    float*       out  = (float*)d_out;           // [1024, 8192] f32

    (void)in_sizes; (void)n_in; (void)out_size;

    psl_prep<<<(KW * OUT_F) / 256, 256>>>(conn, w);

    cudaFuncSetAttribute(psl_main,
                         cudaFuncAttributeMaxDynamicSharedMemorySize,
                         SMEM_BYTES);

    dim3 grid(O_SPLIT, BATCH / BT);   // (8, 128) = 1024 CTAs
    psl_main<<<grid, THREADS, SMEM_BYTES>>>(x, out);
}